// round 7
// baseline (speedup 1.0000x reference)
#include <cuda_runtime.h>

#define NBATCH 2048
#define NT     48
#define NC     35
#define NE     19
#define NH     128
#define RROWS  16
#define NTHR   512
#define NBLK   128
#define NPAIR  665
#define GKC    10
#define GCH    20
#define GRCH   (NH * 4 * 12)      // 6144 raw floats per G chunk (12 = 10 + 2 pad)
#define GDUP   (NH * 84)          // 10752 dup floats per G chunk
#define EKC    6
#define ECH    12
#define ERCH   (672 * EKC)        // 4032 raw floats per E chunk
#define EDUP   (112 * 76)         // 8512 dup floats per E chunk

typedef unsigned long long u64;

// ---------------- prepared weights (device scratch) ----------------
__device__ float PW_G[GCH * GRCH];    // [chunk][u][gate][12]  (k-pad zeroed)
__device__ float PW_E[ECH * ERCH];    // [chunk][pair][6]
__device__ float PW_FRd[NC * NC];
__device__ float PB_Gd[NH * 4];
__device__ float PDXd[NC];
__device__ float g_blk[NBLK * NT * 5];

// ---------------- smem layout (floats) ----------------
#define O_AA   0
#define O_AB   3200
#define O_CT   6400
#define O_DTP  8576
#define O_XM   9136
#define O_XZ   10328
#define O_XCP  11520
#define O_CAT  12080
#define O_TPT  13360
#define O_WDH  24784
#define O_WHR  29264
#define O_WFR  33744
#define O_BIA  34976
#define O_SRED 36448
#define O_WB   36528
#define SMEM_FLOATS (O_WB + 2 * GDUP)   // 58032 -> 232128 B

#define B_BDH 0
#define B_BHR 128
#define B_BFR 168
#define B_BDX 208
#define B_PDX 248
#define B_BCB 288
#define B_PBG 960

// ---------------- helpers ----------------
static __device__ __forceinline__ u64 bcast2(float w) {
    u64 r; asm("mov.b64 %0, {%1, %1};" : "=l"(r) : "f"(w)); return r;
}
static __device__ __forceinline__ void fma2(u64& acc, u64 a, u64 b) {
    asm("fma.rn.f32x2 %0, %1, %2, %0;" : "+l"(acc) : "l"(a), "l"(b));
}
static __device__ __forceinline__ float2 unpack2(u64 v) {
    float2 f; asm("mov.b64 {%0, %1}, %2;" : "=f"(f.x), "=f"(f.y) : "l"(v)); return f;
}
static __device__ __forceinline__ float sigmoidf_(float v) {
    return 1.0f / (1.0f + __expf(-v));
}
static __device__ __forceinline__ float ftanh_(float v) {
    return 1.0f - __fdividef(2.0f, __expf(2.0f * v) + 1.0f);
}

// ---------------- prep ----------------
__global__ void brits_prep(const float* __restrict__ w_fr,
                           const float* __restrict__ w_comb,
                           const float* __restrict__ w_ih,
                           const float* __restrict__ w_hh,
                           const float* __restrict__ b_ih,
                           const float* __restrict__ b_hh,
                           const float* __restrict__ w_dx)
{
    int i0 = blockIdx.x * blockDim.x + threadIdx.x;
    int n = gridDim.x * blockDim.x;
    for (int i = i0; i < GCH * GRCH; i += n) {
        int c = i / GRCH, rem = i - c * GRCH;
        int u = rem / 48, rem2 = rem - u * 48;
        int j = rem2 / 12, kk = rem2 - j * 12;
        int k = c * GKC + kk;
        float v = 0.0f;
        if (kk < GKC) {
            if (k < 70)      v = w_ih[(j * NH + u) * 70 + k];
            else if (k >= 72) v = w_hh[(j * NH + u) * NH + (k - 72)];
        }
        PW_G[i] = v;
    }
    for (int i = i0; i < ECH * ERCH; i += n) {
        int c = i / ERCH, rem = i - c * ERCH;
        int p = rem / EKC, kk = rem - p * EKC;
        int k = c * EKC + kk;
        PW_E[i] = (p < NPAIR && k < 70) ? w_comb[p * 70 + k] : 0.0f;
    }
    for (int i = i0; i < NC * NC; i += n) {
        int r = i / NC, c = i - r * NC;
        PW_FRd[i] = (r == c) ? 0.0f : w_fr[i];
    }
    for (int i = i0; i < NH * 4; i += n) {
        int u = i >> 2, j = i & 3;
        PB_Gd[i] = b_ih[j * NH + u] + b_hh[j * NH + u];
    }
    for (int i = i0; i < NC; i += n) PDXd[i] = w_dx[i * NC + i];
}

// ---------------- main ----------------
__global__ __launch_bounds__(NTHR, 1)
void brits_main(const float* __restrict__ x, const float* __restrict__ mask,
                const float* __restrict__ delta,
                const float* __restrict__ w_dh, const float* __restrict__ b_dh,
                const float* __restrict__ b_dx,
                const float* __restrict__ w_hr, const float* __restrict__ b_hr,
                const float* __restrict__ b_fr,
                const float* __restrict__ b_comb,
                float* __restrict__ out_imp, float* __restrict__ out_ens)
{
    extern __shared__ float sm[];
    float* sAA  = sm + O_AA;
    float* sAB  = sm + O_AB;
    float* sCT  = sm + O_CT;
    float* sDTP = sm + O_DTP;
    float* sXM  = sm + O_XM;
    float* sXZ  = sm + O_XZ;
    float* sXCP = sm + O_XCP;
    float* sCAT = sm + O_CAT;
    float* sTPT = sm + O_TPT;
    float* sWDH = sm + O_WDH;
    float* sWHR = sm + O_WHR;
    float* sWFR = sm + O_WFR;
    float* sBIA = sm + O_BIA;
    float* sRED = sm + O_SRED;
    float* sWB  = sm + O_WB;

    const int tid  = threadIdx.x;
    const int lane = tid & 31;
    const int wrp  = tid >> 5;
    const int rowBase = blockIdx.x * RROWS;

    // one-time resident weights/biases + state init
    for (int i = tid; i < NH * NC; i += NTHR) sWDH[i] = w_dh[i];
    for (int i = tid; i < NC * NH; i += NTHR) sWHR[i] = w_hr[i];
    for (int i = tid; i < NC * NC; i += NTHR) sWFR[i] = PW_FRd[i];
    for (int i = tid; i < NH; i += NTHR) sBIA[B_BDH + i] = b_dh[i];
    for (int i = tid; i < NC; i += NTHR) {
        sBIA[B_BHR + i] = b_hr[i];
        sBIA[B_BFR + i] = b_fr[i];
        sBIA[B_BDX + i] = b_dx[i];
        sBIA[B_PDX + i] = PDXd[i];
    }
    for (int i = tid; i < NPAIR; i += NTHR) sBIA[B_BCB + i] = b_comb[i];
    for (int i = tid; i < NH * 4; i += NTHR) sBIA[B_PBG + i] = PB_Gd[i];
    for (int i = tid; i < 3200; i += NTHR) { sAA[i] = 0.f; sAB[i] = 0.f; }
    for (int i = tid; i < NH * 17; i += NTHR) sCT[i] = 0.f;
    for (int i = tid; i < 160; i += NTHR) sCAT[70 * 16 + i] = 0.f;
    __syncthreads();

    float* aCur = sAA;
    float* aNxt = sAB;

    const int pgrp = tid >> 2;          // E: 6-pair group (valid < 112 -> tid < 448)
    const int r0e  = (tid & 3) * 4;
    const int uG   = tid >> 2;          // G: LSTM unit
    const int r0g  = (tid & 3) * 4;

    // precomputed dup-copy destinations (fixed per thread)
    int gDst[6], eDst[4];
    #pragma unroll
    for (int i = 0; i < 6; ++i) {
        int o = (tid + i * NTHR) * 2;
        int u = o / 48, rem = o - u * 48;
        int j = rem / 12, kk = rem - j * 12;
        gDst[i] = (kk < GKC) ? (u * 84 + j * 20 + kk * 2) : -1;
    }
    #pragma unroll
    for (int i = 0; i < 4; ++i) {
        int idx2 = tid + i * NTHR;
        if (idx2 < ERCH / 2) {
            int o = idx2 * 2;
            int p = o / 6, kk = o - p * 6;
            eDst[i] = (p / 6) * 76 + (p - (p / 6) * 6) * 12 + kk * 2;
        } else eDst[i] = -1;
    }

    for (int t = 0; t < NT; ++t) {
        float lm = 0.f, l1 = 0.f, l2 = 0.f, lq = 0.f, l4 = 0.f;

        // ---- A: transposed loads ----
        for (int i = tid; i < RROWS * NC; i += NTHR) {
            int r = i / NC, c = i - r * NC;
            size_t gi = ((size_t)(rowBase + r) * NT + t) * NC + c;
            float xv = x[gi], mv = mask[gi], dv = delta[gi];
            sDTP[c * 16 + r] = dv;
            sXM[(c * 17 + r) * 2 + 0] = xv;
            sXM[(c * 17 + r) * 2 + 1] = mv;
            sCAT[(NC + c) * 16 + r] = mv;
            lm += mv;
        }
        __syncthreads();

        // ---- B1: gamma_x ----
        for (int i = tid; i < NC * 16; i += NTHR) {
            int c = i >> 4, r = i & 15;
            float gx = __expf(-fmaxf(sDTP[c * 16 + r] * sBIA[B_PDX + c]
                                     + sBIA[B_BDX + c], 0.f));
            sCAT[c * 16 + r] = gx;
        }
        // ---- B2: gamma_h decay ----
        for (int task = tid; task < NH * 8; task += NTHR) {
            int h = task >> 3, rg = task & 7, r0 = rg * 2;
            u64 a0 = 0ull, a1 = 0ull;
            const float* wr = sWDH + h * NC;
            #pragma unroll
            for (int k = 0; k < NC; ++k) {
                u64 d = *reinterpret_cast<const u64*>(&sDTP[k * 16 + r0]);
                if (k & 1) fma2(a1, d, bcast2(wr[k]));
                else       fma2(a0, d, bcast2(wr[k]));
            }
            float2 s0 = unpack2(a0), s1 = unpack2(a1);
            float bb = sBIA[B_BDH + h];
            aCur[(72 + h) * 16 + r0 + 0] *= __expf(-fmaxf(s0.x + s1.x + bb, 0.f));
            aCur[(72 + h) * 16 + r0 + 1] *= __expf(-fmaxf(s0.y + s1.y + bb, 0.f));
        }
        __syncthreads();

        // ---- C: x_h ----
        if (tid < NC * 8) {
            int c = tid >> 3, rg = tid & 7, r0 = rg * 2;
            u64 a0 = 0ull, a1 = 0ull;
            const float* wr = sWHR + c * NH;
            #pragma unroll 4
            for (int k0 = 0; k0 < NH; k0 += 4) {
                float4 w = *reinterpret_cast<const float4*>(wr + k0);
                u64 h0 = *reinterpret_cast<const u64*>(&aCur[(72 + k0 + 0) * 16 + r0]);
                u64 h1 = *reinterpret_cast<const u64*>(&aCur[(72 + k0 + 1) * 16 + r0]);
                u64 h2 = *reinterpret_cast<const u64*>(&aCur[(72 + k0 + 2) * 16 + r0]);
                u64 h3 = *reinterpret_cast<const u64*>(&aCur[(72 + k0 + 3) * 16 + r0]);
                fma2(a0, h0, bcast2(w.x)); fma2(a1, h1, bcast2(w.y));
                fma2(a0, h2, bcast2(w.z)); fma2(a1, h3, bcast2(w.w));
            }
            float2 s0 = unpack2(a0), s1 = unpack2(a1);
            float bb = sBIA[B_BHR + c];
            float xh[2] = {s0.x + s1.x + bb, s0.y + s1.y + bb};
            #pragma unroll
            for (int rr = 0; rr < 2; ++rr) {
                int r = r0 + rr;
                sXZ[(c * 17 + r) * 2 + 0] = xh[rr];
                float xt = sXM[(c * 17 + r) * 2 + 0];
                float mt = sXM[(c * 17 + r) * 2 + 1];
                l1 += fabsf(xt - xh[rr]) * mt;
                sXCP[c * 16 + r] = mt * xt + (1.f - mt) * xh[rr];
            }
        }
        __syncthreads();

        // ---- D: z_h ----
        if (tid < NC * 8) {
            int c = tid >> 3, rg = tid & 7, r0 = rg * 2;
            u64 a0 = 0ull, a1 = 0ull;
            const float* wr = sWFR + c * NC;
            #pragma unroll
            for (int k = 0; k < NC; ++k) {
                u64 xp = *reinterpret_cast<const u64*>(&sXCP[k * 16 + r0]);
                if (k & 1) fma2(a1, xp, bcast2(wr[k]));
                else       fma2(a0, xp, bcast2(wr[k]));
            }
            float2 s0 = unpack2(a0), s1 = unpack2(a1);
            float bb = sBIA[B_BFR + c];
            #pragma unroll
            for (int rr = 0; rr < 2; ++rr) {
                int r = r0 + rr;
                float z = ((rr == 0) ? (s0.x + s1.x) : (s0.y + s1.y)) + bb;
                float xh = sXZ[(c * 17 + r) * 2 + 0];
                sXZ[(c * 17 + r) * 2 + 1] = z - xh;
                float xt = sXM[(c * 17 + r) * 2 + 0];
                float mt = sXM[(c * 17 + r) * 2 + 1];
                l2 += fabsf(xt - z) * mt;
            }
        }
        __syncthreads();

        // ---- E: alpha GEMM (dup weights via LDS.64, no bcast) ----
        {
            u64 acc[6][2];
            #pragma unroll
            for (int j = 0; j < 6; ++j) { acc[j][0] = 0ull; acc[j][1] = 0ull; }
            float2 pre[4];
            {
                const float2* s = reinterpret_cast<const float2*>(PW_E);
                #pragma unroll
                for (int i = 0; i < 4; ++i)
                    if (tid + i * NTHR < ERCH / 2) pre[i] = s[tid + i * NTHR];
            }
            for (int ch = 0; ch < ECH; ++ch) {
                float* wb = sWB + (ch & 1) * GDUP;
                #pragma unroll
                for (int i = 0; i < 4; ++i) {
                    int d = eDst[i];
                    if (d >= 0) {
                        float4 v = make_float4(pre[i].x, pre[i].x, pre[i].y, pre[i].y);
                        *reinterpret_cast<float4*>(wb + d) = v;
                    }
                }
                if (ch + 1 < ECH) {
                    const float2* s = reinterpret_cast<const float2*>(PW_E + (ch + 1) * ERCH);
                    #pragma unroll
                    for (int i = 0; i < 4; ++i)
                        if (tid + i * NTHR < ERCH / 2) pre[i] = s[tid + i * NTHR];
                }
                __syncthreads();
                if (tid < 448) {
                    const float* wrow = wb + pgrp * 76;
                    int kbase = ch * EKC;
                    #pragma unroll
                    for (int kk = 0; kk < EKC; ++kk) {
                        ulonglong2 a2 = *reinterpret_cast<const ulonglong2*>(
                            &sCAT[(kbase + kk) * 16 + r0e]);
                        #pragma unroll
                        for (int j = 0; j < 6; ++j) {
                            u64 w = *reinterpret_cast<const u64*>(wrow + j * 12 + kk * 2);
                            fma2(acc[j][0], a2.x, w);
                            fma2(acc[j][1], a2.y, w);
                        }
                    }
                }
            }
            // epilogue
            if (tid < 448) {
                #pragma unroll
                for (int j = 0; j < 6; ++j) {
                    int p = pgrp * 6 + j;
                    if (p < NPAIR) {
                        int n = p / NC, c = p - n * NC;
                        float bc = sBIA[B_BCB + p];
                        float qn = (float)(n + 1) * 0.05f;
                        #pragma unroll
                        for (int pp = 0; pp < 2; ++pp) {
                            float2 av = unpack2(acc[j][pp]);
                            #pragma unroll
                            for (int rr = 0; rr < 2; ++rr) {
                                int r = r0e + pp * 2 + rr;
                                float alpha = ((rr == 0) ? av.x : av.y) + bc;
                                float xh  = sXZ[(c * 17 + r) * 2 + 0];
                                float dzh = sXZ[(c * 17 + r) * 2 + 1];
                                float tp = xh + alpha * dzh;
                                float xt = sXM[(c * 17 + r) * 2 + 0];
                                float mt = sXM[(c * 17 + r) * 2 + 1];
                                float wq = (xt <= tp) ? (1.f - qn) : qn;
                                lq += fabsf(tp - xt) * mt * wq;
                                sTPT[p * 17 + r] = tp;
                            }
                        }
                    }
                }
            }
        }
        __syncthreads();

        // ---- F: ensemble mean, imp out, cc2 ----
        for (int i = tid; i < NC * 16; i += NTHR) {
            int c = i >> 4, r = i & 15;
            float s = 0.f;
            #pragma unroll
            for (int n = 0; n < NE; ++n) s += sTPT[(n * NC + c) * 17 + r];
            float mean = s * (1.0f / (float)NE);
            float xt = sXM[(c * 17 + r) * 2 + 0];
            float mt = sXM[(c * 17 + r) * 2 + 1];
            l4 += fabsf(xt - mean) * mt;
            float cc = mt * xt + (1.f - mt) * mean;
            out_imp[((size_t)(rowBase + r) * NT + t) * NC + c] = cc;
            aCur[c * 16 + r] = cc;
            aCur[(NC + c) * 16 + r] = mt;
        }
        // ---- ens writes ----
        for (int i = tid; i < RROWS * NPAIR; i += NTHR) {
            int r = i / NPAIR, pn = i - r * NPAIR;
            int n = pn / NC, c = pn - n * NC;
            float tp = sTPT[pn * 17 + r];
            float xt = sXM[(c * 17 + r) * 2 + 0];
            float mt = sXM[(c * 17 + r) * 2 + 1];
            out_ens[(((size_t)(rowBase + r) * NE + n) * NT + t) * NC + c]
                = mt * xt + (1.f - mt) * tp;
        }
        // ---- loss reduce ----
        {
            float v0 = lm, v1 = l1, v2 = l2, v3 = lq, v4 = l4;
            #pragma unroll
            for (int o = 16; o > 0; o >>= 1) {
                v0 += __shfl_down_sync(0xffffffffu, v0, o);
                v1 += __shfl_down_sync(0xffffffffu, v1, o);
                v2 += __shfl_down_sync(0xffffffffu, v2, o);
                v3 += __shfl_down_sync(0xffffffffu, v3, o);
                v4 += __shfl_down_sync(0xffffffffu, v4, o);
            }
            if (lane == 0) {
                sRED[wrp * 5 + 0] = v0; sRED[wrp * 5 + 1] = v1;
                sRED[wrp * 5 + 2] = v2; sRED[wrp * 5 + 3] = v3;
                sRED[wrp * 5 + 4] = v4;
            }
        }
        __syncthreads();
        if (tid == 0) {
            float s0 = 0.f, s1 = 0.f, s2 = 0.f, s3 = 0.f, s4 = 0.f;
            for (int w = 0; w < NTHR / 32; ++w) {
                s0 += sRED[w * 5 + 0]; s1 += sRED[w * 5 + 1];
                s2 += sRED[w * 5 + 2]; s3 += sRED[w * 5 + 3];
                s4 += sRED[w * 5 + 4];
            }
            float* gp = g_blk + ((size_t)blockIdx.x * NT + t) * 5;
            gp[0] = s0; gp[1] = s1; gp[2] = s2; gp[3] = s3; gp[4] = s4;
        }

        // ---- G: LSTM gates GEMM + fused cell update (dup weights) ----
        {
            u64 acc[4][2];
            #pragma unroll
            for (int j = 0; j < 4; ++j) { acc[j][0] = 0ull; acc[j][1] = 0ull; }
            float2 pre[6];
            {
                const float2* s = reinterpret_cast<const float2*>(PW_G);
                #pragma unroll
                for (int i = 0; i < 6; ++i) pre[i] = s[tid + i * NTHR];
            }
            for (int ch = 0; ch < GCH; ++ch) {
                float* wb = sWB + (ch & 1) * GDUP;
                #pragma unroll
                for (int i = 0; i < 6; ++i) {
                    int d = gDst[i];
                    if (d >= 0) {
                        float4 v = make_float4(pre[i].x, pre[i].x, pre[i].y, pre[i].y);
                        *reinterpret_cast<float4*>(wb + d) = v;
                    }
                }
                if (ch + 1 < GCH) {
                    const float2* s = reinterpret_cast<const float2*>(PW_G + (ch + 1) * GRCH);
                    #pragma unroll
                    for (int i = 0; i < 6; ++i) pre[i] = s[tid + i * NTHR];
                }
                __syncthreads();
                const float* wrow = wb + uG * 84;
                int kbase = ch * GKC;
                #pragma unroll
                for (int kk = 0; kk < GKC; ++kk) {
                    ulonglong2 a2 = *reinterpret_cast<const ulonglong2*>(
                        &aCur[(kbase + kk) * 16 + r0g]);
                    u64 w0 = *reinterpret_cast<const u64*>(wrow + 0 * 20 + kk * 2);
                    u64 w1 = *reinterpret_cast<const u64*>(wrow + 1 * 20 + kk * 2);
                    u64 w2 = *reinterpret_cast<const u64*>(wrow + 2 * 20 + kk * 2);
                    u64 w3 = *reinterpret_cast<const u64*>(wrow + 3 * 20 + kk * 2);
                    fma2(acc[0][0], a2.x, w0); fma2(acc[0][1], a2.y, w0);
                    fma2(acc[1][0], a2.x, w1); fma2(acc[1][1], a2.y, w1);
                    fma2(acc[2][0], a2.x, w2); fma2(acc[2][1], a2.y, w2);
                    fma2(acc[3][0], a2.x, w3); fma2(acc[3][1], a2.y, w3);
                }
            }
            // epilogue: cell update
            float bi = sBIA[B_PBG + uG * 4 + 0];
            float bf = sBIA[B_PBG + uG * 4 + 1];
            float bg = sBIA[B_PBG + uG * 4 + 2];
            float bo = sBIA[B_PBG + uG * 4 + 3];
            #pragma unroll
            for (int pp = 0; pp < 2; ++pp) {
                float2 gi2 = unpack2(acc[0][pp]);
                float2 gf2 = unpack2(acc[1][pp]);
                float2 gg2 = unpack2(acc[2][pp]);
                float2 go2 = unpack2(acc[3][pp]);
                #pragma unroll
                for (int rr = 0; rr < 2; ++rr) {
                    int r = r0g + pp * 2 + rr;
                    float gi_ = ((rr == 0) ? gi2.x : gi2.y) + bi;
                    float gf_ = ((rr == 0) ? gf2.x : gf2.y) + bf;
                    float gg_ = ((rr == 0) ? gg2.x : gg2.y) + bg;
                    float go_ = ((rr == 0) ? go2.x : go2.y) + bo;
                    float cn = sigmoidf_(gf_) * sCT[uG * 17 + r]
                             + sigmoidf_(gi_) * ftanh_(gg_);
                    sCT[uG * 17 + r] = cn;
                    aNxt[(72 + uG) * 16 + r] = sigmoidf_(go_) * ftanh_(cn);
                }
            }
        }
        __syncthreads();
        float* tmp = aCur; aCur = aNxt; aNxt = tmp;
    }
}

__global__ void brits_finalize(float* __restrict__ out)
{
    __shared__ double terms[NT];
    int w = threadIdx.x >> 5, lane = threadIdx.x & 31;
    for (int t = w; t < NT; t += 16) {
        double s0 = 0.0, s1 = 0.0, s2 = 0.0, s3 = 0.0, s4 = 0.0;
        for (int b = lane; b < NBLK; b += 32) {
            const float* gp = g_blk + ((size_t)b * NT + t) * 5;
            s0 += (double)gp[0]; s1 += (double)gp[1]; s2 += (double)gp[2];
            s3 += (double)gp[3]; s4 += (double)gp[4];
        }
        #pragma unroll
        for (int o = 16; o > 0; o >>= 1) {
            s0 += __shfl_down_sync(0xffffffffu, s0, o);
            s1 += __shfl_down_sync(0xffffffffu, s1, o);
            s2 += __shfl_down_sync(0xffffffffu, s2, o);
            s3 += __shfl_down_sync(0xffffffffu, s3, o);
            s4 += __shfl_down_sync(0xffffffffu, s4, o);
        }
        if (lane == 0) {
            double pm = s0 + 1e-5;
            terms[t] = (s1 + s2 + s4 + s3 / (double)NE) / pm;
        }
    }
    __syncthreads();
    if (threadIdx.x == 0) {
        double s = 0.0;
        for (int i = 0; i < NT; ++i) s += terms[i];
        out[0] = (float)(s / (double)NT);
    }
}

extern "C" void kernel_launch(void* const* d_in, const int* in_sizes, int n_in,
                              void* d_out, int out_size)
{
    const float* x      = (const float*)d_in[0];
    const float* mask   = (const float*)d_in[1];
    const float* delta  = (const float*)d_in[2];
    const float* w_dh   = (const float*)d_in[3];
    const float* b_dh   = (const float*)d_in[4];
    const float* w_dx   = (const float*)d_in[5];
    const float* b_dx   = (const float*)d_in[6];
    const float* w_hr   = (const float*)d_in[7];
    const float* b_hr   = (const float*)d_in[8];
    const float* w_fr   = (const float*)d_in[9];
    const float* b_fr   = (const float*)d_in[10];
    const float* w_comb = (const float*)d_in[11];
    const float* b_comb = (const float*)d_in[12];
    const float* w_ih   = (const float*)d_in[13];
    const float* w_hh   = (const float*)d_in[14];
    const float* b_ih   = (const float*)d_in[15];
    const float* b_hh   = (const float*)d_in[16];

    float* out = (float*)d_out;
    float* out_imp = out + 1;
    float* out_ens = out_imp + (size_t)NBATCH * NT * NC;

    const int smem_bytes = SMEM_FLOATS * (int)sizeof(float);
    cudaFuncSetAttribute(brits_main, cudaFuncAttributeMaxDynamicSharedMemorySize,
                         smem_bytes);

    brits_prep<<<256, 256>>>(w_fr, w_comb, w_ih, w_hh, b_ih, b_hh, w_dx);
    brits_main<<<NBLK, NTHR, smem_bytes>>>(
        x, mask, delta, w_dh, b_dh, b_dx, w_hr, b_hr, b_fr, b_comb,
        out_imp, out_ens);
    brits_finalize<<<1, 512>>>(out);
}